// round 3
// baseline (speedup 1.0000x reference)
#include <cuda_runtime.h>
#include <math.h>

#define Nn 4096
#define INF_ 512
#define Hh 128
#define OUTd 40
#define CAP 128
#define MAXIT 300
#define TOLf 3e-6f
#define KAPPAf 0.8f
#define LNEPS 1e-5f

// ---------------- device scratch (no allocations allowed) ----------------
__device__ float g_h[Nn * Hh];        // encoder output, node-major
__device__ float g_T[Nn * Hh];        // Omega1 @ U, node-major
__device__ float g_B[Nn * Hh];        // bias term B, node-major
__device__ float g_Xbuf[2 * Nn * Hh]; // ping-pong X, node-major
__device__ float g_Wpt[Hh * Hh];      // Wp transposed: Wpt[m*H+i] = Wp[i][m]
__device__ float g_O1t[Hh * Hh];      // Omega1 transposed
__device__ float g_WencT[INF_ * Hh];  // W_enc transposed [IN][H]
__device__ int   g_cnt16[Nn * 16];
__device__ int   g_off16[Nn * 16];
__device__ int   g_ccnt[Nn];
__device__ int   g_cidx[Nn * CAP];
__device__ float g_cval[Nn * CAP];
__device__ float g_err[MAXIT];
__device__ unsigned g_bar_count;
__device__ volatile unsigned g_bar_gen;
__device__ int   g_final;

// ---------------- software grid barrier (all blocks resident) ----------------
__device__ __forceinline__ void grid_sync(unsigned nb) {
    __syncthreads();
    if (threadIdx.x == 0) {
        unsigned gen = g_bar_gen;
        __threadfence();
        if (atomicAdd(&g_bar_count, 1u) == nb - 1u) {
            g_bar_count = 0u;
            __threadfence();
            g_bar_gen = gen + 1u;
        } else {
            while (g_bar_gen == gen) { __nanosleep(64); }
        }
        __threadfence();
    }
    __syncthreads();
}

__device__ __forceinline__ void bar_group(int g) {
    // named barrier per 128-thread group (ids 1,2)
    asm volatile("bar.sync %0, %1;" :: "r"(g + 1), "r"(128) : "memory");
}

// ---------------- init: X from X_0 (transpose), zero err/barrier ----------------
__global__ void k_init(const float* __restrict__ X0) {
    int t = blockIdx.x * blockDim.x + threadIdx.x;
    if (t < Nn * Hh) {
        int j = t >> 7, i = t & 127;
        g_Xbuf[t] = X0[(size_t)i * Nn + j];
    }
    if (t < MAXIT) g_err[t] = 0.f;
    if (t == 0) { g_bar_count = 0u; g_bar_gen = 0u; g_final = 0; }
}

// ---------------- transposes of W_enc and Omega1 ----------------
__global__ void k_prep(const float* __restrict__ Wenc, const float* __restrict__ O1) {
    int t = blockIdx.x * blockDim.x + threadIdx.x;
    if (t < INF_ * Hh) {
        int k = t >> 7, i = t & 127;
        g_WencT[t] = Wenc[(size_t)i * INF_ + k];
    }
    if (t < Hh * Hh) {
        int m = t >> 7, i = t & 127;
        g_O1t[t] = O1[i * Hh + m];
    }
}

// ---------------- L1-ball row projection of W (exact reference algorithm) ----------------
__global__ void k_proj(const float* __restrict__ W) {
    int r = threadIdx.x;
    if (r >= Hh) return;
    float a[Hh], s[Hh];
    float sum = 0.f;
    for (int c = 0; c < Hh; c++) { float w = W[r * Hh + c]; a[c] = fabsf(w); sum += a[c]; }
    bool doproj = sum > KAPPAf;
    float theta = 0.f;
    if (doproj) {
        for (int c = 0; c < Hh; c++) s[c] = a[c];
        for (int c = 1; c < Hh; c++) {           // insertion sort, descending
            float key = s[c]; int d = c - 1;
            while (d >= 0 && s[d] < key) { s[d + 1] = s[d]; d--; }
            s[d + 1] = key;
        }
        int rho = 0; float css = 0.f;
        for (int jj = 0; jj < Hh; jj++) { css += s[jj]; if (s[jj] * (float)(jj + 1) > css - KAPPAf) rho++; }
        float cr = 0.f;
        for (int jj = 0; jj < rho; jj++) cr += s[jj];
        theta = (cr - KAPPAf) / (float)rho;
    }
    for (int c = 0; c < Hh; c++) {
        float w = W[r * Hh + c];
        float p = doproj ? copysignf(fmaxf(a[c] - theta, 0.f), w) : w;
        g_Wpt[c * Hh + r] = p;   // transposed layout
    }
}

// ---------------- sparse CSC extraction from dense adj (deterministic) ----------------
__global__ void k_cnt(const float* __restrict__ adj) {
    int t = blockIdx.x * blockDim.x + threadIdx.x;
    if (t >= Nn * 16) return;
    int j = t & (Nn - 1);
    int c = t >> 12;
    int k0 = c * (Nn / 16);
    int cnt = 0;
    for (int k = k0; k < k0 + Nn / 16; k++)
        cnt += (adj[(size_t)k * Nn + j] != 0.f);
    g_cnt16[j * 16 + c] = cnt;
}

__global__ void k_off() {
    int j = blockIdx.x * blockDim.x + threadIdx.x;
    if (j >= Nn) return;
    int off = 0;
    for (int c = 0; c < 16; c++) { g_off16[j * 16 + c] = off; off += g_cnt16[j * 16 + c]; }
    g_ccnt[j] = off > CAP ? CAP : off;
}

__global__ void k_fill(const float* __restrict__ adj) {
    int t = blockIdx.x * blockDim.x + threadIdx.x;
    if (t >= Nn * 16) return;
    int j = t & (Nn - 1);
    int c = t >> 12;
    int k0 = c * (Nn / 16);
    int p = j * CAP + g_off16[j * 16 + c];
    int pend = j * CAP + CAP;
    for (int k = k0; k < k0 + Nn / 16; k++) {
        float v = adj[(size_t)k * Nn + j];
        if (v != 0.f && p < pend) { g_cidx[p] = k; g_cval[p] = v; p++; }
    }
}

// ---------------- encoder: h = gelu(LN(x @ W_enc^T + b_enc)) ----------------
__global__ void __launch_bounds__(128) k_enc(const float* __restrict__ x,
                                             const float* __restrict__ benc,
                                             const float* __restrict__ lng,
                                             const float* __restrict__ lnb) {
    __shared__ float xs[8 * INF_];
    __shared__ float rs[4], rq[4];
    int i = threadIdx.x;
    int jb = blockIdx.x * 8;
    for (int n = 0; n < 8; n++)
        for (int k = i; k < INF_; k += 128)
            xs[n * INF_ + k] = x[(size_t)(jb + n) * INF_ + k];
    __syncthreads();
    float acc[8];
    float bi = benc[i];
#pragma unroll
    for (int n = 0; n < 8; n++) acc[n] = bi;
    for (int k = 0; k < INF_; k++) {
        float w = g_WencT[k * Hh + i];
#pragma unroll
        for (int n = 0; n < 8; n++) acc[n] += w * xs[n * INF_ + k];
    }
    float gi = lng[i], bbi = lnb[i];
    int lane = i & 31, wid = i >> 5;
    for (int n = 0; n < 8; n++) {
        float s = acc[n], q = acc[n] * acc[n];
#pragma unroll
        for (int o = 16; o > 0; o >>= 1) {
            s += __shfl_xor_sync(0xffffffffu, s, o);
            q += __shfl_xor_sync(0xffffffffu, q, o);
        }
        if (lane == 0) { rs[wid] = s; rq[wid] = q; }
        __syncthreads();
        float ts = rs[0] + rs[1] + rs[2] + rs[3];
        float tq = rq[0] + rq[1] + rq[2] + rq[3];
        float mu = ts * (1.f / 128.f);
        float var = tq * (1.f / 128.f) - mu * mu;
        float v = (acc[n] - mu) * rsqrtf(var + LNEPS) * gi + bbi;
        float ge = 0.5f * v * (1.f + erff(v * 0.70710678118654752f));
        g_h[(size_t)(jb + n) * Hh + i] = ge;
        __syncthreads();
    }
}

// ---------------- persistent fixed-point kernel ----------------
// dyn smem: [0,16384)            : W (Omega1^T then Wp^T), conflict-free layout
//           [16384, 16384+1024)  : group s-buffers (2 groups x 4 nodes x 128)
#define FP_SMEM ((Hh * Hh + 2 * 4 * Hh) * (int)sizeof(float))

extern __shared__ float dsm[];

__global__ void __launch_bounds__(256, 2) k_fp() {
    float* Wsm = dsm;
    float* sb = dsm + Hh * Hh;
    const int tid = threadIdx.x;
    const int g = tid >> 7;
    const int i = tid & 127;
    float* sbg = sb + g * 4 * Hh;
    const unsigned nb = gridDim.x;
    const int ngroups = (int)nb * 2;
    const int gg = blockIdx.x * 2 + g;

    // ---- stage 0a: T = Omega1 @ U (node-local matvec) ----
    for (int t = tid; t < Hh * Hh; t += 256) Wsm[t] = g_O1t[t];
    __syncthreads();
    for (int base = gg * 4; base < Nn; base += ngroups * 4) {
#pragma unroll
        for (int n = 0; n < 4; n++) sbg[n * Hh + i] = g_h[(size_t)(base + n) * Hh + i];
        bar_group(g);
        float a0 = 0.f, a1 = 0.f, a2 = 0.f, a3 = 0.f;
#pragma unroll 16
        for (int m = 0; m < Hh; m++) {
            float w = Wsm[m * Hh + i];
            a0 += w * sbg[0 * Hh + m];
            a1 += w * sbg[1 * Hh + m];
            a2 += w * sbg[2 * Hh + m];
            a3 += w * sbg[3 * Hh + m];
        }
        g_T[(size_t)(base + 0) * Hh + i] = a0;
        g_T[(size_t)(base + 1) * Hh + i] = a1;
        g_T[(size_t)(base + 2) * Hh + i] = a2;
        g_T[(size_t)(base + 3) * Hh + i] = a3;
        bar_group(g);
    }
    grid_sync(nb);

    // swap W in smem to Wp^T
    for (int t = tid; t < Hh * Hh; t += 256) Wsm[t] = g_Wpt[t];
    __syncthreads();

    // ---- stage 0b: B = T @ adj via CSC gather (same node mapping as iterations,
    //      so B[j] is produced and consumed by the same threads -> no grid sync) ----
    for (int base = gg * 4; base < Nn; base += ngroups * 4) {
#pragma unroll
        for (int n = 0; n < 4; n++) {
            int j = base + n;
            int cnt = g_ccnt[j];
            const int* ci = g_cidx + j * CAP;
            const float* cv = g_cval + j * CAP;
            float s = 0.f;
#pragma unroll 4
            for (int p = 0; p < cnt; p++) s += cv[p] * g_T[(size_t)ci[p] * Hh + i];
            g_B[(size_t)j * Hh + i] = s;
        }
    }

    // ---- Picard iterations: X <- relu(Wp (X A) + B), 1 grid barrier / iter ----
    int wrote = 0;
    for (int it = 0; it < MAXIT; ++it) {
        const float* Xr = g_Xbuf + (size_t)(it & 1) * Nn * Hh;
        float* Xw = g_Xbuf + (size_t)((it & 1) ^ 1) * Nn * Hh;
        float lerr = 0.f;
        for (int base = gg * 4; base < Nn; base += ngroups * 4) {
#pragma unroll
            for (int n = 0; n < 4; n++) {
                int j = base + n;
                int cnt = g_ccnt[j];
                const int* ci = g_cidx + j * CAP;
                const float* cv = g_cval + j * CAP;
                float s = 0.f;
#pragma unroll 4
                for (int p = 0; p < cnt; p++) s += cv[p] * Xr[(size_t)ci[p] * Hh + i];
                sbg[n * Hh + i] = s;
            }
            bar_group(g);
            float a0 = g_B[(size_t)(base + 0) * Hh + i];
            float a1 = g_B[(size_t)(base + 1) * Hh + i];
            float a2 = g_B[(size_t)(base + 2) * Hh + i];
            float a3 = g_B[(size_t)(base + 3) * Hh + i];
#pragma unroll 16
            for (int m = 0; m < Hh; m++) {
                float w = Wsm[m * Hh + i];
                a0 += w * sbg[0 * Hh + m];
                a1 += w * sbg[1 * Hh + m];
                a2 += w * sbg[2 * Hh + m];
                a3 += w * sbg[3 * Hh + m];
            }
#pragma unroll
            for (int n = 0; n < 4; n++) {
                float an = (n == 0) ? a0 : (n == 1) ? a1 : (n == 2) ? a2 : a3;
                float xn = fmaxf(an, 0.f);
                float d = fabsf(xn - Xr[(size_t)(base + n) * Hh + i]);
                lerr = fmaxf(lerr, d);
                Xw[(size_t)(base + n) * Hh + i] = xn;
            }
            bar_group(g);
        }
#pragma unroll
        for (int o = 16; o > 0; o >>= 1)
            lerr = fmaxf(lerr, __shfl_xor_sync(0xffffffffu, lerr, o));
        if ((tid & 31) == 0)
            atomicMax((unsigned*)&g_err[it], __float_as_uint(lerr));
        wrote = (it & 1) ^ 1;
        grid_sync(nb);
        if (g_err[it] < TOLf) break;
    }
    if (blockIdx.x == 0 && tid == 0) g_final = wrote;
}

// ---------------- epilogue: out = LN(h + X) @ W_V^T + b_V ----------------
__global__ void __launch_bounds__(128) k_epi(const float* __restrict__ Wv,
                                             const float* __restrict__ bv,
                                             const float* __restrict__ lng,
                                             const float* __restrict__ lnb,
                                             float* __restrict__ out) {
    __shared__ float vs[Hh];
    __shared__ float rs[4], rq[4];
    int i = threadIdx.x;
    int j = blockIdx.x;
    const float* Xf = g_Xbuf + (size_t)g_final * Nn * Hh;
    float v = g_h[(size_t)j * Hh + i] + Xf[(size_t)j * Hh + i];
    float s = v, q = v * v;
    int lane = i & 31, wid = i >> 5;
#pragma unroll
    for (int o = 16; o > 0; o >>= 1) {
        s += __shfl_xor_sync(0xffffffffu, s, o);
        q += __shfl_xor_sync(0xffffffffu, q, o);
    }
    if (lane == 0) { rs[wid] = s; rq[wid] = q; }
    __syncthreads();
    float ts = rs[0] + rs[1] + rs[2] + rs[3];
    float tq = rq[0] + rq[1] + rq[2] + rq[3];
    float mu = ts * (1.f / 128.f);
    float var = tq * (1.f / 128.f) - mu * mu;
    float t = (v - mu) * rsqrtf(var + LNEPS) * lng[i] + lnb[i];
    vs[i] = t;
    __syncthreads();
    if (i < OUTd) {
        float a = bv[i];
#pragma unroll 8
        for (int m = 0; m < Hh; m++) a += Wv[i * Hh + m] * vs[m];
        out[(size_t)j * OUTd + i] = a;
    }
}

// ---------------- host launch ----------------
extern "C" void kernel_launch(void* const* d_in, const int* in_sizes, int n_in,
                              void* d_out, int out_size) {
    const float* x    = (const float*)d_in[0];
    const float* adj  = (const float*)d_in[3];
    const float* Wenc = (const float*)d_in[4];
    const float* benc = (const float*)d_in[5];
    const float* lng  = (const float*)d_in[6];
    const float* lnb  = (const float*)d_in[7];
    const float* W    = (const float*)d_in[8];
    const float* O1   = (const float*)d_in[9];
    const float* Wv   = (const float*)d_in[10];
    const float* bv   = (const float*)d_in[11];
    const float* X0   = (const float*)d_in[12];
    float* out = (float*)d_out;

    cudaFuncSetAttribute(k_fp, cudaFuncAttributeMaxDynamicSharedMemorySize, FP_SMEM);

    int nsm = 148;
    cudaDeviceGetAttribute(&nsm, cudaDevAttrMultiProcessorCount, 0);
    int maxb = 1;
    cudaOccupancyMaxActiveBlocksPerMultiprocessor(&maxb, k_fp, 256, FP_SMEM);
    if (maxb < 1) maxb = 1;
    int per = maxb < 2 ? maxb : 2;
    int nb = nsm * per;

    k_init<<<(Nn * Hh + 255) / 256, 256>>>(X0);
    k_prep<<<(INF_ * Hh + 255) / 256, 256>>>(Wenc, O1);
    k_proj<<<1, 128>>>(W);
    k_cnt<<<(Nn * 16) / 256, 256>>>(adj);
    k_off<<<Nn / 256, 256>>>();
    k_fill<<<(Nn * 16) / 256, 256>>>(adj);
    k_enc<<<Nn / 8, 128>>>(x, benc, lng, lnb);
    k_fp<<<nb, 256, FP_SMEM>>>();
    k_epi<<<Nn, 128>>>(Wv, bv, lng, lnb, out);
}

// round 4
// speedup vs baseline: 1.5639x; 1.5639x over previous
#include <cuda_runtime.h>
#include <math.h>

#define Nn 4096
#define INF_ 512
#define Hh 128
#define OUTd 40
#define CAP 128
#define MAXIT 300
#define TOLf 3e-6f
#define KAPPAf 0.8f
#define LNEPS 1e-5f

// ---------------- device scratch (no allocations allowed) ----------------
__device__ float g_h[Nn * Hh];        // encoder output, node-major
__device__ float g_T[Nn * Hh];        // Omega1 @ U, node-major
__device__ float g_B[Nn * Hh];        // bias term B, node-major
__device__ float g_Xbuf[2 * Nn * Hh]; // ping-pong X, node-major
__device__ float g_Wpt[Hh * Hh];      // Wp transposed: Wpt[m*H+i] = Wp[i][m]
__device__ float g_O1t[Hh * Hh];      // Omega1 transposed
__device__ float g_WencT[INF_ * Hh];  // W_enc transposed [IN][H]
__device__ int   g_cnt16[Nn * 16];
__device__ int   g_off16[Nn * 16];
__device__ int   g_ccnt[Nn];
__device__ int   g_cidx[Nn * CAP];
__device__ float g_cval[Nn * CAP];
__device__ float g_err[MAXIT];
__device__ unsigned g_bar_count;
__device__ volatile unsigned g_bar_gen;
__device__ int   g_final;

// ---------------- software grid barrier (all blocks resident) ----------------
__device__ __forceinline__ void grid_sync(unsigned nb) {
    __syncthreads();
    if (threadIdx.x == 0) {
        unsigned gen = g_bar_gen;
        __threadfence();
        if (atomicAdd(&g_bar_count, 1u) == nb - 1u) {
            g_bar_count = 0u;
            __threadfence();
            g_bar_gen = gen + 1u;
        } else {
            while (g_bar_gen == gen) { __nanosleep(64); }
        }
        __threadfence();
    }
    __syncthreads();
}

__device__ __forceinline__ void bar_group(int g) {
    // named barrier per 128-thread group (ids 1,2)
    asm volatile("bar.sync %0, %1;" :: "r"(g + 1), "r"(128) : "memory");
}

// ---------------- init: X from X_0 (transpose), zero err/barrier ----------------
__global__ void k_init(const float* __restrict__ X0) {
    int t = blockIdx.x * blockDim.x + threadIdx.x;
    if (t < Nn * Hh) {
        int j = t >> 7, i = t & 127;
        g_Xbuf[t] = X0[(size_t)i * Nn + j];
    }
    if (t < MAXIT) g_err[t] = 0.f;
    if (t == 0) { g_bar_count = 0u; g_bar_gen = 0u; g_final = 0; }
}

// ---------------- transposes of W_enc and Omega1 ----------------
__global__ void k_prep(const float* __restrict__ Wenc, const float* __restrict__ O1) {
    int t = blockIdx.x * blockDim.x + threadIdx.x;
    if (t < INF_ * Hh) {
        int k = t >> 7, i = t & 127;
        g_WencT[t] = Wenc[(size_t)i * INF_ + k];
    }
    if (t < Hh * Hh) {
        int m = t >> 7, i = t & 127;
        g_O1t[t] = O1[i * Hh + m];
    }
}

// ---------------- L1-ball row projection of W (exact reference algorithm) ----------------
__global__ void k_proj(const float* __restrict__ W) {
    int r = threadIdx.x;
    if (r >= Hh) return;
    float a[Hh], s[Hh];
    float sum = 0.f;
    for (int c = 0; c < Hh; c++) { float w = W[r * Hh + c]; a[c] = fabsf(w); sum += a[c]; }
    bool doproj = sum > KAPPAf;
    float theta = 0.f;
    if (doproj) {
        for (int c = 0; c < Hh; c++) s[c] = a[c];
        for (int c = 1; c < Hh; c++) {           // insertion sort, descending
            float key = s[c]; int d = c - 1;
            while (d >= 0 && s[d] < key) { s[d + 1] = s[d]; d--; }
            s[d + 1] = key;
        }
        int rho = 0; float css = 0.f;
        for (int jj = 0; jj < Hh; jj++) { css += s[jj]; if (s[jj] * (float)(jj + 1) > css - KAPPAf) rho++; }
        float cr = 0.f;
        for (int jj = 0; jj < rho; jj++) cr += s[jj];
        theta = (cr - KAPPAf) / (float)rho;
    }
    for (int c = 0; c < Hh; c++) {
        float w = W[r * Hh + c];
        float p = doproj ? copysignf(fmaxf(a[c] - theta, 0.f), w) : w;
        g_Wpt[c * Hh + r] = p;   // transposed layout
    }
}

// ---------------- sparse CSC extraction from dense adj (deterministic) ----------------
__global__ void k_cnt(const float* __restrict__ adj) {
    int t = blockIdx.x * blockDim.x + threadIdx.x;
    if (t >= Nn * 16) return;
    int j = t & (Nn - 1);
    int c = t >> 12;
    int k0 = c * (Nn / 16);
    int cnt = 0;
    for (int k = k0; k < k0 + Nn / 16; k++)
        cnt += (adj[(size_t)k * Nn + j] != 0.f);
    g_cnt16[j * 16 + c] = cnt;
}

__global__ void k_off() {
    int j = blockIdx.x * blockDim.x + threadIdx.x;
    if (j >= Nn) return;
    int off = 0;
    for (int c = 0; c < 16; c++) { g_off16[j * 16 + c] = off; off += g_cnt16[j * 16 + c]; }
    g_ccnt[j] = off > CAP ? CAP : off;
}

__global__ void k_fill(const float* __restrict__ adj) {
    int t = blockIdx.x * blockDim.x + threadIdx.x;
    if (t >= Nn * 16) return;
    int j = t & (Nn - 1);
    int c = t >> 12;
    int k0 = c * (Nn / 16);
    int p = j * CAP + g_off16[j * 16 + c];
    int pend = j * CAP + CAP;
    for (int k = k0; k < k0 + Nn / 16; k++) {
        float v = adj[(size_t)k * Nn + j];
        if (v != 0.f && p < pend) { g_cidx[p] = k; g_cval[p] = v; p++; }
    }
}

// ---------------- encoder: h = gelu(LN(x @ W_enc^T + b_enc)) ----------------
__global__ void __launch_bounds__(128) k_enc(const float* __restrict__ x,
                                             const float* __restrict__ benc,
                                             const float* __restrict__ lng,
                                             const float* __restrict__ lnb) {
    __shared__ float xs[8 * INF_];
    __shared__ float rs[4], rq[4];
    int i = threadIdx.x;
    int jb = blockIdx.x * 8;
    for (int n = 0; n < 8; n++)
        for (int k = i; k < INF_; k += 128)
            xs[n * INF_ + k] = x[(size_t)(jb + n) * INF_ + k];
    __syncthreads();
    float acc[8];
    float bi = benc[i];
#pragma unroll
    for (int n = 0; n < 8; n++) acc[n] = bi;
    for (int k = 0; k < INF_; k++) {
        float w = g_WencT[k * Hh + i];
#pragma unroll
        for (int n = 0; n < 8; n++) acc[n] += w * xs[n * INF_ + k];
    }
    float gi = lng[i], bbi = lnb[i];
    int lane = i & 31, wid = i >> 5;
    for (int n = 0; n < 8; n++) {
        float s = acc[n], q = acc[n] * acc[n];
#pragma unroll
        for (int o = 16; o > 0; o >>= 1) {
            s += __shfl_xor_sync(0xffffffffu, s, o);
            q += __shfl_xor_sync(0xffffffffu, q, o);
        }
        if (lane == 0) { rs[wid] = s; rq[wid] = q; }
        __syncthreads();
        float ts = rs[0] + rs[1] + rs[2] + rs[3];
        float tq = rq[0] + rq[1] + rq[2] + rq[3];
        float mu = ts * (1.f / 128.f);
        float var = tq * (1.f / 128.f) - mu * mu;
        float v = (acc[n] - mu) * rsqrtf(var + LNEPS) * gi + bbi;
        float ge = 0.5f * v * (1.f + erff(v * 0.70710678118654752f));
        g_h[(size_t)(jb + n) * Hh + i] = ge;
        __syncthreads();
    }
}

// ---------------- persistent fixed-point kernel ----------------
// dyn smem: [0,16384)            : W (Omega1^T then Wp^T), conflict-free layout
//           [16384, 16384+1024)  : group s-buffers (2 groups x 4 nodes x 128)
#define FP_SMEM ((Hh * Hh + 2 * 4 * Hh) * (int)sizeof(float))

extern __shared__ float dsm[];

__global__ void __launch_bounds__(256, 2) k_fp() {
    float* Wsm = dsm;
    float* sb = dsm + Hh * Hh;
    const int tid = threadIdx.x;
    const int g = tid >> 7;
    const int i = tid & 127;
    float* sbg = sb + g * 4 * Hh;
    const unsigned nb = gridDim.x;
    const int ngroups = (int)nb * 2;
    const int gg = blockIdx.x * 2 + g;

    // ---- stage 0a: T = Omega1 @ U (node-local matvec) ----
    for (int t = tid; t < Hh * Hh; t += 256) Wsm[t] = g_O1t[t];
    __syncthreads();
    for (int base = gg * 4; base < Nn; base += ngroups * 4) {
#pragma unroll
        for (int n = 0; n < 4; n++) sbg[n * Hh + i] = g_h[(size_t)(base + n) * Hh + i];
        bar_group(g);
        float a0 = 0.f, a1 = 0.f, a2 = 0.f, a3 = 0.f;
#pragma unroll 16
        for (int m = 0; m < Hh; m++) {
            float w = Wsm[m * Hh + i];
            a0 += w * sbg[0 * Hh + m];
            a1 += w * sbg[1 * Hh + m];
            a2 += w * sbg[2 * Hh + m];
            a3 += w * sbg[3 * Hh + m];
        }
        g_T[(size_t)(base + 0) * Hh + i] = a0;
        g_T[(size_t)(base + 1) * Hh + i] = a1;
        g_T[(size_t)(base + 2) * Hh + i] = a2;
        g_T[(size_t)(base + 3) * Hh + i] = a3;
        bar_group(g);
    }
    grid_sync(nb);

    // swap W in smem to Wp^T
    for (int t = tid; t < Hh * Hh; t += 256) Wsm[t] = g_Wpt[t];
    __syncthreads();

    // ---- stage 0b: B = T @ adj via CSC gather (same node mapping as iterations,
    //      so B[j] is produced and consumed by the same threads -> no grid sync) ----
    for (int base = gg * 4; base < Nn; base += ngroups * 4) {
#pragma unroll
        for (int n = 0; n < 4; n++) {
            int j = base + n;
            int cnt = g_ccnt[j];
            const int* ci = g_cidx + j * CAP;
            const float* cv = g_cval + j * CAP;
            float s = 0.f;
#pragma unroll 4
            for (int p = 0; p < cnt; p++) s += cv[p] * g_T[(size_t)ci[p] * Hh + i];
            g_B[(size_t)j * Hh + i] = s;
        }
    }

    // ---- Picard iterations: X <- relu(Wp (X A) + B), 1 grid barrier / iter ----
    int wrote = 0;
    for (int it = 0; it < MAXIT; ++it) {
        const float* Xr = g_Xbuf + (size_t)(it & 1) * Nn * Hh;
        float* Xw = g_Xbuf + (size_t)((it & 1) ^ 1) * Nn * Hh;
        float lerr = 0.f;
        for (int base = gg * 4; base < Nn; base += ngroups * 4) {
#pragma unroll
            for (int n = 0; n < 4; n++) {
                int j = base + n;
                int cnt = g_ccnt[j];
                const int* ci = g_cidx + j * CAP;
                const float* cv = g_cval + j * CAP;
                float s = 0.f;
#pragma unroll 4
                for (int p = 0; p < cnt; p++) s += cv[p] * Xr[(size_t)ci[p] * Hh + i];
                sbg[n * Hh + i] = s;
            }
            bar_group(g);
            float a0 = g_B[(size_t)(base + 0) * Hh + i];
            float a1 = g_B[(size_t)(base + 1) * Hh + i];
            float a2 = g_B[(size_t)(base + 2) * Hh + i];
            float a3 = g_B[(size_t)(base + 3) * Hh + i];
#pragma unroll 16
            for (int m = 0; m < Hh; m++) {
                float w = Wsm[m * Hh + i];
                a0 += w * sbg[0 * Hh + m];
                a1 += w * sbg[1 * Hh + m];
                a2 += w * sbg[2 * Hh + m];
                a3 += w * sbg[3 * Hh + m];
            }
#pragma unroll
            for (int n = 0; n < 4; n++) {
                float an = (n == 0) ? a0 : (n == 1) ? a1 : (n == 2) ? a2 : a3;
                float xn = fmaxf(an, 0.f);
                float d = fabsf(xn - Xr[(size_t)(base + n) * Hh + i]);
                lerr = fmaxf(lerr, d);
                Xw[(size_t)(base + n) * Hh + i] = xn;
            }
            bar_group(g);
        }
#pragma unroll
        for (int o = 16; o > 0; o >>= 1)
            lerr = fmaxf(lerr, __shfl_xor_sync(0xffffffffu, lerr, o));
        if ((tid & 31) == 0)
            atomicMax((unsigned*)&g_err[it], __float_as_uint(lerr));
        wrote = (it & 1) ^ 1;
        grid_sync(nb);
        if (g_err[it] < TOLf) break;
    }
    if (blockIdx.x == 0 && tid == 0) g_final = wrote;
}

// ---------------- epilogue: out = LN(h + X) @ W_V^T + b_V ----------------
__global__ void __launch_bounds__(128) k_epi(const float* __restrict__ Wv,
                                             const float* __restrict__ bv,
                                             const float* __restrict__ lng,
                                             const float* __restrict__ lnb,
                                             float* __restrict__ out) {
    __shared__ float vs[Hh];
    __shared__ float rs[4], rq[4];
    int i = threadIdx.x;
    int j = blockIdx.x;
    const float* Xf = g_Xbuf + (size_t)g_final * Nn * Hh;
    float v = g_h[(size_t)j * Hh + i] + Xf[(size_t)j * Hh + i];
    float s = v, q = v * v;
    int lane = i & 31, wid = i >> 5;
#pragma unroll
    for (int o = 16; o > 0; o >>= 1) {
        s += __shfl_xor_sync(0xffffffffu, s, o);
        q += __shfl_xor_sync(0xffffffffu, q, o);
    }
    if (lane == 0) { rs[wid] = s; rq[wid] = q; }
    __syncthreads();
    float ts = rs[0] + rs[1] + rs[2] + rs[3];
    float tq = rq[0] + rq[1] + rq[2] + rq[3];
    float mu = ts * (1.f / 128.f);
    float var = tq * (1.f / 128.f) - mu * mu;
    float t = (v - mu) * rsqrtf(var + LNEPS) * lng[i] + lnb[i];
    vs[i] = t;
    __syncthreads();
    if (i < OUTd) {
        float a = bv[i];
#pragma unroll 8
        for (int m = 0; m < Hh; m++) a += Wv[i * Hh + m] * vs[m];
        out[(size_t)j * OUTd + i] = a;
    }
}

// ---------------- host launch ----------------
extern "C" void kernel_launch(void* const* d_in, const int* in_sizes, int n_in,
                              void* d_out, int out_size) {
    const float* x    = (const float*)d_in[0];
    const float* adj  = (const float*)d_in[3];
    const float* Wenc = (const float*)d_in[4];
    const float* benc = (const float*)d_in[5];
    const float* lng  = (const float*)d_in[6];
    const float* lnb  = (const float*)d_in[7];
    const float* W    = (const float*)d_in[8];
    const float* O1   = (const float*)d_in[9];
    const float* Wv   = (const float*)d_in[10];
    const float* bv   = (const float*)d_in[11];
    const float* X0   = (const float*)d_in[12];
    float* out = (float*)d_out;

    cudaFuncSetAttribute(k_fp, cudaFuncAttributeMaxDynamicSharedMemorySize, FP_SMEM);

    int nsm = 148;
    cudaDeviceGetAttribute(&nsm, cudaDevAttrMultiProcessorCount, 0);
    int maxb = 1;
    cudaOccupancyMaxActiveBlocksPerMultiprocessor(&maxb, k_fp, 256, FP_SMEM);
    if (maxb < 1) maxb = 1;
    int per = maxb < 2 ? maxb : 2;
    int nb = nsm * per;

    k_init<<<(Nn * Hh + 255) / 256, 256>>>(X0);
    k_prep<<<(INF_ * Hh + 255) / 256, 256>>>(Wenc, O1);
    k_proj<<<1, 128>>>(W);
    k_cnt<<<(Nn * 16) / 256, 256>>>(adj);
    k_off<<<Nn / 256, 256>>>();
    k_fill<<<(Nn * 16) / 256, 256>>>(adj);
    k_enc<<<Nn / 8, 128>>>(x, benc, lng, lnb);
    k_fp<<<nb, 256, FP_SMEM>>>();
    k_epi<<<Nn, 128>>>(Wv, bv, lng, lnb, out);
}

// round 5
// speedup vs baseline: 1.5678x; 1.0025x over previous
#include <cuda_runtime.h>
#include <math.h>

#define Nn 4096
#define INF_ 512
#define Hh 128
#define OUTd 40
#define CAP 128
#define MAXIT 300
#define TOLf 3e-6f
#define KAPPAf 0.8f
#define LNEPS 1e-5f

// ---------------- device scratch (no allocations allowed) ----------------
__device__ float g_h[Nn * Hh];        // encoder output, node-major
__device__ float g_T[Nn * Hh];        // Omega1 @ U, node-major
__device__ float g_B[Nn * Hh];        // bias term B, node-major
__device__ float g_Xbuf[2 * Nn * Hh]; // ping-pong X, node-major
__device__ float g_Wpt[Hh * Hh];      // Wp transposed: Wpt[m*H+i] = Wp[i][m]
__device__ float g_O1t[Hh * Hh];      // Omega1 transposed
__device__ float g_WencT[INF_ * Hh];  // W_enc transposed [IN][H]
__device__ int   g_cnt16[Nn * 16];
__device__ int   g_off16[Nn * 16];
__device__ int   g_ccnt[Nn];
__device__ int   g_cidx[Nn * CAP];
__device__ float g_cval[Nn * CAP];
__device__ float g_err[MAXIT];
__device__ unsigned g_bar_count;
__device__ volatile unsigned g_bar_gen;
__device__ int   g_final;

// ---------------- software grid barrier (all blocks resident) ----------------
__device__ __forceinline__ void grid_sync(unsigned nb) {
    __syncthreads();
    if (threadIdx.x == 0) {
        unsigned gen = g_bar_gen;
        __threadfence();
        if (atomicAdd(&g_bar_count, 1u) == nb - 1u) {
            g_bar_count = 0u;
            __threadfence();
            g_bar_gen = gen + 1u;
        } else {
            while (g_bar_gen == gen) { __nanosleep(64); }
        }
        __threadfence();
    }
    __syncthreads();
}

__device__ __forceinline__ void bar_group(int g) {
    // named barrier per 128-thread group (ids 1,2)
    asm volatile("bar.sync %0, %1;" :: "r"(g + 1), "r"(128) : "memory");
}

// ---------------- init: X from X_0 (transpose), zero err/barrier ----------------
__global__ void k_init(const float* __restrict__ X0) {
    int t = blockIdx.x * blockDim.x + threadIdx.x;
    if (t < Nn * Hh) {
        int j = t >> 7, i = t & 127;
        g_Xbuf[t] = X0[(size_t)i * Nn + j];
    }
    if (t < MAXIT) g_err[t] = 0.f;
    if (t == 0) { g_bar_count = 0u; g_bar_gen = 0u; g_final = 0; }
}

// ---------------- transposes of W_enc and Omega1 ----------------
__global__ void k_prep(const float* __restrict__ Wenc, const float* __restrict__ O1) {
    int t = blockIdx.x * blockDim.x + threadIdx.x;
    if (t < INF_ * Hh) {
        int k = t >> 7, i = t & 127;
        g_WencT[t] = Wenc[(size_t)i * INF_ + k];
    }
    if (t < Hh * Hh) {
        int m = t >> 7, i = t & 127;
        g_O1t[t] = O1[i * Hh + m];
    }
}

// ---------------- L1-ball row projection of W (exact reference algorithm) ----------------
__global__ void k_proj(const float* __restrict__ W) {
    int r = threadIdx.x;
    if (r >= Hh) return;
    float a[Hh], s[Hh];
    float sum = 0.f;
    for (int c = 0; c < Hh; c++) { float w = W[r * Hh + c]; a[c] = fabsf(w); sum += a[c]; }
    bool doproj = sum > KAPPAf;
    float theta = 0.f;
    if (doproj) {
        for (int c = 0; c < Hh; c++) s[c] = a[c];
        for (int c = 1; c < Hh; c++) {           // insertion sort, descending
            float key = s[c]; int d = c - 1;
            while (d >= 0 && s[d] < key) { s[d + 1] = s[d]; d--; }
            s[d + 1] = key;
        }
        int rho = 0; float css = 0.f;
        for (int jj = 0; jj < Hh; jj++) { css += s[jj]; if (s[jj] * (float)(jj + 1) > css - KAPPAf) rho++; }
        float cr = 0.f;
        for (int jj = 0; jj < rho; jj++) cr += s[jj];
        theta = (cr - KAPPAf) / (float)rho;
    }
    for (int c = 0; c < Hh; c++) {
        float w = W[r * Hh + c];
        float p = doproj ? copysignf(fmaxf(a[c] - theta, 0.f), w) : w;
        g_Wpt[c * Hh + r] = p;   // transposed layout
    }
}

// ---------------- sparse CSC extraction from dense adj (deterministic) ----------------
__global__ void k_cnt(const float* __restrict__ adj) {
    int t = blockIdx.x * blockDim.x + threadIdx.x;
    if (t >= Nn * 16) return;
    int j = t & (Nn - 1);
    int c = t >> 12;
    int k0 = c * (Nn / 16);
    int cnt = 0;
    for (int k = k0; k < k0 + Nn / 16; k++)
        cnt += (adj[(size_t)k * Nn + j] != 0.f);
    g_cnt16[j * 16 + c] = cnt;
}

__global__ void k_off() {
    int j = blockIdx.x * blockDim.x + threadIdx.x;
    if (j >= Nn) return;
    int off = 0;
    for (int c = 0; c < 16; c++) { g_off16[j * 16 + c] = off; off += g_cnt16[j * 16 + c]; }
    g_ccnt[j] = off > CAP ? CAP : off;
}

__global__ void k_fill(const float* __restrict__ adj) {
    int t = blockIdx.x * blockDim.x + threadIdx.x;
    if (t >= Nn * 16) return;
    int j = t & (Nn - 1);
    int c = t >> 12;
    int k0 = c * (Nn / 16);
    int p = j * CAP + g_off16[j * 16 + c];
    int pend = j * CAP + CAP;
    for (int k = k0; k < k0 + Nn / 16; k++) {
        float v = adj[(size_t)k * Nn + j];
        if (v != 0.f && p < pend) { g_cidx[p] = k; g_cval[p] = v; p++; }
    }
}

// ---------------- encoder: h = gelu(LN(x @ W_enc^T + b_enc)) ----------------
__global__ void __launch_bounds__(128) k_enc(const float* __restrict__ x,
                                             const float* __restrict__ benc,
                                             const float* __restrict__ lng,
                                             const float* __restrict__ lnb) {
    __shared__ float xs[8 * INF_];
    __shared__ float rs[4], rq[4];
    int i = threadIdx.x;
    int jb = blockIdx.x * 8;
    for (int n = 0; n < 8; n++)
        for (int k = i; k < INF_; k += 128)
            xs[n * INF_ + k] = x[(size_t)(jb + n) * INF_ + k];
    __syncthreads();
    float acc[8];
    float bi = benc[i];
#pragma unroll
    for (int n = 0; n < 8; n++) acc[n] = bi;
    for (int k = 0; k < INF_; k++) {
        float w = g_WencT[k * Hh + i];
#pragma unroll
        for (int n = 0; n < 8; n++) acc[n] += w * xs[n * INF_ + k];
    }
    float gi = lng[i], bbi = lnb[i];
    int lane = i & 31, wid = i >> 5;
    for (int n = 0; n < 8; n++) {
        float s = acc[n], q = acc[n] * acc[n];
#pragma unroll
        for (int o = 16; o > 0; o >>= 1) {
            s += __shfl_xor_sync(0xffffffffu, s, o);
            q += __shfl_xor_sync(0xffffffffu, q, o);
        }
        if (lane == 0) { rs[wid] = s; rq[wid] = q; }
        __syncthreads();
        float ts = rs[0] + rs[1] + rs[2] + rs[3];
        float tq = rq[0] + rq[1] + rq[2] + rq[3];
        float mu = ts * (1.f / 128.f);
        float var = tq * (1.f / 128.f) - mu * mu;
        float v = (acc[n] - mu) * rsqrtf(var + LNEPS) * gi + bbi;
        float ge = 0.5f * v * (1.f + erff(v * 0.70710678118654752f));
        g_h[(size_t)(jb + n) * Hh + i] = ge;
        __syncthreads();
    }
}

// ---------------- persistent fixed-point kernel ----------------
// dyn smem: [0,16384)            : W (Omega1^T then Wp^T), conflict-free layout
//           [16384, 16384+1024)  : group s-buffers (2 groups x 4 nodes x 128)
#define FP_SMEM ((Hh * Hh + 2 * 4 * Hh) * (int)sizeof(float))

extern __shared__ float dsm[];

__global__ void __launch_bounds__(256, 2) k_fp() {
    float* Wsm = dsm;
    float* sb = dsm + Hh * Hh;
    const int tid = threadIdx.x;
    const int g = tid >> 7;
    const int i = tid & 127;
    float* sbg = sb + g * 4 * Hh;
    const unsigned nb = gridDim.x;
    const int ngroups = (int)nb * 2;
    const int gg = blockIdx.x * 2 + g;

    // ---- stage 0a: T = Omega1 @ U (node-local matvec) ----
    for (int t = tid; t < Hh * Hh; t += 256) Wsm[t] = g_O1t[t];
    __syncthreads();
    for (int base = gg * 4; base < Nn; base += ngroups * 4) {
#pragma unroll
        for (int n = 0; n < 4; n++) sbg[n * Hh + i] = g_h[(size_t)(base + n) * Hh + i];
        bar_group(g);
        float a0 = 0.f, a1 = 0.f, a2 = 0.f, a3 = 0.f;
#pragma unroll 16
        for (int m = 0; m < Hh; m++) {
            float w = Wsm[m * Hh + i];
            a0 += w * sbg[0 * Hh + m];
            a1 += w * sbg[1 * Hh + m];
            a2 += w * sbg[2 * Hh + m];
            a3 += w * sbg[3 * Hh + m];
        }
        g_T[(size_t)(base + 0) * Hh + i] = a0;
        g_T[(size_t)(base + 1) * Hh + i] = a1;
        g_T[(size_t)(base + 2) * Hh + i] = a2;
        g_T[(size_t)(base + 3) * Hh + i] = a3;
        bar_group(g);
    }
    grid_sync(nb);

    // swap W in smem to Wp^T
    for (int t = tid; t < Hh * Hh; t += 256) Wsm[t] = g_Wpt[t];
    __syncthreads();

    // ---- stage 0b: B = T @ adj via CSC gather (same node mapping as iterations,
    //      so B[j] is produced and consumed by the same threads -> no grid sync) ----
    for (int base = gg * 4; base < Nn; base += ngroups * 4) {
#pragma unroll
        for (int n = 0; n < 4; n++) {
            int j = base + n;
            int cnt = g_ccnt[j];
            const int* ci = g_cidx + j * CAP;
            const float* cv = g_cval + j * CAP;
            float s = 0.f;
#pragma unroll 4
            for (int p = 0; p < cnt; p++) s += cv[p] * g_T[(size_t)ci[p] * Hh + i];
            g_B[(size_t)j * Hh + i] = s;
        }
    }

    // ---- Picard iterations: X <- relu(Wp (X A) + B), 1 grid barrier / iter ----
    int wrote = 0;
    for (int it = 0; it < MAXIT; ++it) {
        const float* Xr = g_Xbuf + (size_t)(it & 1) * Nn * Hh;
        float* Xw = g_Xbuf + (size_t)((it & 1) ^ 1) * Nn * Hh;
        float lerr = 0.f;
        for (int base = gg * 4; base < Nn; base += ngroups * 4) {
#pragma unroll
            for (int n = 0; n < 4; n++) {
                int j = base + n;
                int cnt = g_ccnt[j];
                const int* ci = g_cidx + j * CAP;
                const float* cv = g_cval + j * CAP;
                float s = 0.f;
#pragma unroll 4
                for (int p = 0; p < cnt; p++) s += cv[p] * Xr[(size_t)ci[p] * Hh + i];
                sbg[n * Hh + i] = s;
            }
            bar_group(g);
            float a0 = g_B[(size_t)(base + 0) * Hh + i];
            float a1 = g_B[(size_t)(base + 1) * Hh + i];
            float a2 = g_B[(size_t)(base + 2) * Hh + i];
            float a3 = g_B[(size_t)(base + 3) * Hh + i];
#pragma unroll 16
            for (int m = 0; m < Hh; m++) {
                float w = Wsm[m * Hh + i];
                a0 += w * sbg[0 * Hh + m];
                a1 += w * sbg[1 * Hh + m];
                a2 += w * sbg[2 * Hh + m];
                a3 += w * sbg[3 * Hh + m];
            }
#pragma unroll
            for (int n = 0; n < 4; n++) {
                float an = (n == 0) ? a0 : (n == 1) ? a1 : (n == 2) ? a2 : a3;
                float xn = fmaxf(an, 0.f);
                float d = fabsf(xn - Xr[(size_t)(base + n) * Hh + i]);
                lerr = fmaxf(lerr, d);
                Xw[(size_t)(base + n) * Hh + i] = xn;
            }
            bar_group(g);
        }
#pragma unroll
        for (int o = 16; o > 0; o >>= 1)
            lerr = fmaxf(lerr, __shfl_xor_sync(0xffffffffu, lerr, o));
        if ((tid & 31) == 0)
            atomicMax((unsigned*)&g_err[it], __float_as_uint(lerr));
        wrote = (it & 1) ^ 1;
        grid_sync(nb);
        if (g_err[it] < TOLf) break;
    }
    if (blockIdx.x == 0 && tid == 0) g_final = wrote;
}

// ---------------- epilogue: out = LN(h + X) @ W_V^T + b_V ----------------
__global__ void __launch_bounds__(128) k_epi(const float* __restrict__ Wv,
                                             const float* __restrict__ bv,
                                             const float* __restrict__ lng,
                                             const float* __restrict__ lnb,
                                             float* __restrict__ out) {
    __shared__ float vs[Hh];
    __shared__ float rs[4], rq[4];
    int i = threadIdx.x;
    int j = blockIdx.x;
    const float* Xf = g_Xbuf + (size_t)g_final * Nn * Hh;
    float v = g_h[(size_t)j * Hh + i] + Xf[(size_t)j * Hh + i];
    float s = v, q = v * v;
    int lane = i & 31, wid = i >> 5;
#pragma unroll
    for (int o = 16; o > 0; o >>= 1) {
        s += __shfl_xor_sync(0xffffffffu, s, o);
        q += __shfl_xor_sync(0xffffffffu, q, o);
    }
    if (lane == 0) { rs[wid] = s; rq[wid] = q; }
    __syncthreads();
    float ts = rs[0] + rs[1] + rs[2] + rs[3];
    float tq = rq[0] + rq[1] + rq[2] + rq[3];
    float mu = ts * (1.f / 128.f);
    float var = tq * (1.f / 128.f) - mu * mu;
    float t = (v - mu) * rsqrtf(var + LNEPS) * lng[i] + lnb[i];
    vs[i] = t;
    __syncthreads();
    if (i < OUTd) {
        float a = bv[i];
#pragma unroll 8
        for (int m = 0; m < Hh; m++) a += Wv[i * Hh + m] * vs[m];
        out[(size_t)j * OUTd + i] = a;
    }
}

// ---------------- host launch ----------------
extern "C" void kernel_launch(void* const* d_in, const int* in_sizes, int n_in,
                              void* d_out, int out_size) {
    const float* x    = (const float*)d_in[0];
    const float* adj  = (const float*)d_in[3];
    const float* Wenc = (const float*)d_in[4];
    const float* benc = (const float*)d_in[5];
    const float* lng  = (const float*)d_in[6];
    const float* lnb  = (const float*)d_in[7];
    const float* W    = (const float*)d_in[8];
    const float* O1   = (const float*)d_in[9];
    const float* Wv   = (const float*)d_in[10];
    const float* bv   = (const float*)d_in[11];
    const float* X0   = (const float*)d_in[12];
    float* out = (float*)d_out;

    cudaFuncSetAttribute(k_fp, cudaFuncAttributeMaxDynamicSharedMemorySize, FP_SMEM);

    int nsm = 148;
    cudaDeviceGetAttribute(&nsm, cudaDevAttrMultiProcessorCount, 0);
    int maxb = 1;
    cudaOccupancyMaxActiveBlocksPerMultiprocessor(&maxb, k_fp, 256, FP_SMEM);
    if (maxb < 1) maxb = 1;
    int per = maxb < 2 ? maxb : 2;
    int nb = nsm * per;

    k_init<<<(Nn * Hh + 255) / 256, 256>>>(X0);
    k_prep<<<(INF_ * Hh + 255) / 256, 256>>>(Wenc, O1);
    k_proj<<<1, 128>>>(W);
    k_cnt<<<(Nn * 16) / 256, 256>>>(adj);
    k_off<<<Nn / 256, 256>>>();
    k_fill<<<(Nn * 16) / 256, 256>>>(adj);
    k_enc<<<Nn / 8, 128>>>(x, benc, lng, lnb);
    k_fp<<<nb, 256, FP_SMEM>>>();
    k_epi<<<Nn, 128>>>(Wv, bv, lng, lnb, out);
}